// round 3
// baseline (speedup 1.0000x reference)
#include <cuda_runtime.h>
#include <cstdint>
#include <cstddef>

#define DI __device__ __forceinline__

constexpr int Bn = 8, Nn = 1024, Dn = 256, Hn = 4;
constexpr int ROWS = Bn * Nn;  // 8192

// -------- scratch (static device globals: allocation-free) --------
__device__ float g_Q[ROWS * Dn];
__device__ float g_K[ROWS * Dn];
__device__ float g_V[ROWS * Dn];
__device__ float g_M[ROWS * Dn];
__device__ float g_S[(size_t)Bn * Hn * Nn * Nn];  // 134 MB score scratch

// -------- packed f32x2 helpers --------
DI unsigned long long pack2(float lo, float hi) {
    unsigned long long r;
    asm("mov.b64 %0, {%1, %2};" : "=l"(r) : "f"(lo), "f"(hi));
    return r;
}
DI void fma2(unsigned long long& d, unsigned long long a, unsigned long long b) {
    asm("fma.rn.f32x2 %0, %1, %2, %0;" : "+l"(d) : "l"(a), "l"(b));
}
DI float2 unpack2(unsigned long long v) {
    float lo, hi;
    asm("mov.b64 {%0, %1}, %2;" : "=f"(lo), "=f"(hi) : "l"(v));
    return make_float2(lo, hi);
}

// monotone float->uint mapping (order-preserving)
DI unsigned mapf(float x) {
    unsigned b = __float_as_uint(x);
    return (b & 0x80000000u) ? ~b : (b | 0x80000000u);
}
DI float invmap(unsigned u) {
    unsigned b = (u & 0x80000000u) ? (u & 0x7FFFFFFFu) : ~u;
    return __uint_as_float(b);
}

// ============================================================================
// GEMM: C[m,n] = sum_k A[m*256+k] * W[n*256+k] + bias[n]
// M=8192, N=256, K=256. CTA tile 128x128, BK=16, 256 thr, 8x8/thread.
// ============================================================================
__global__ void __launch_bounds__(256, 2) gemm256_kernel(
    const float* __restrict__ A, const float* __restrict__ W,
    const float* __restrict__ bias, float* __restrict__ C)
{
    __shared__ __align__(16) float As[16][132];
    __shared__ __align__(16) float Bs[16][132];

    const int tid  = threadIdx.x;
    const int m0   = blockIdx.y * 128;
    const int n0   = blockIdx.x * 128;
    const int trow = (tid >> 4) << 3;
    const int c0   = (tid & 15) << 2;
    const int r    = tid >> 2;
    const int q    = (tid & 3) << 2;

    unsigned long long acc[8][4];
#pragma unroll
    for (int i = 0; i < 8; ++i)
#pragma unroll
        for (int p = 0; p < 4; ++p) acc[i][p] = 0ULL;

    for (int kb = 0; kb < 256; kb += 16) {
        __syncthreads();
#pragma unroll
        for (int l = 0; l < 2; ++l) {
            int rr = r + 64 * l;
            float4 av = *(const float4*)(A + (size_t)(m0 + rr) * 256 + kb + q);
            float4 wv = *(const float4*)(W + (size_t)(n0 + rr) * 256 + kb + q);
            As[q + 0][rr] = av.x; As[q + 1][rr] = av.y;
            As[q + 2][rr] = av.z; As[q + 3][rr] = av.w;
            Bs[q + 0][rr] = wv.x; Bs[q + 1][rr] = wv.y;
            Bs[q + 2][rr] = wv.z; Bs[q + 3][rr] = wv.w;
        }
        __syncthreads();
#pragma unroll
        for (int kk = 0; kk < 16; ++kk) {
            float4 a0 = *(const float4*)&As[kk][trow];
            float4 a1 = *(const float4*)&As[kk][trow + 4];
            ulonglong2 b0 = *(const ulonglong2*)&Bs[kk][c0];
            ulonglong2 b1 = *(const ulonglong2*)&Bs[kk][c0 + 64];
            unsigned long long ad[8];
            ad[0] = pack2(a0.x, a0.x); ad[1] = pack2(a0.y, a0.y);
            ad[2] = pack2(a0.z, a0.z); ad[3] = pack2(a0.w, a0.w);
            ad[4] = pack2(a1.x, a1.x); ad[5] = pack2(a1.y, a1.y);
            ad[6] = pack2(a1.z, a1.z); ad[7] = pack2(a1.w, a1.w);
#pragma unroll
            for (int i = 0; i < 8; ++i) {
                fma2(acc[i][0], ad[i], b0.x);
                fma2(acc[i][1], ad[i], b0.y);
                fma2(acc[i][2], ad[i], b1.x);
                fma2(acc[i][3], ad[i], b1.y);
            }
        }
    }

    float4 bb0 = *(const float4*)&bias[n0 + c0];
    float4 bb1 = *(const float4*)&bias[n0 + c0 + 64];
#pragma unroll
    for (int i = 0; i < 8; ++i) {
        int m = m0 + trow + i;
        float2 v0 = unpack2(acc[i][0]), v1 = unpack2(acc[i][1]);
        float2 v2 = unpack2(acc[i][2]), v3 = unpack2(acc[i][3]);
        float4 o0 = make_float4(v0.x + bb0.x, v0.y + bb0.y, v1.x + bb0.z, v1.y + bb0.w);
        float4 o1 = make_float4(v2.x + bb1.x, v2.y + bb1.y, v3.x + bb1.z, v3.y + bb1.w);
        *(float4*)&C[(size_t)m * 256 + n0 + c0]      = o0;
        *(float4*)&C[(size_t)m * 256 + n0 + c0 + 64] = o1;
    }
}

// ============================================================================
// Scores: S[b,h,i,j] = 0.125*dot(Q_i, K_j) - 0.1*td[b,i,j]
// CTA tile 128x128, FULL K=64 staged in smem (one sync), 8x8/thread.
// Dynamic smem: As[64][132] + Bs[64][132] = 67584 B.
// ============================================================================
constexpr int SCORES_SMEM = 64 * 132 * 4 * 2;

__global__ void __launch_bounds__(256, 2) scores_kernel(const float* __restrict__ td)
{
    extern __shared__ __align__(16) float smem[];
    float* As = smem;               // [64][132] (k-major, transposed)
    float* Bs = smem + 64 * 132;

    const int tid  = threadIdx.x;
    const int bh   = blockIdx.z;
    const int b    = bh >> 2;
    const int h    = bh & 3;
    const int i0   = blockIdx.y * 128;
    const int j0   = blockIdx.x * 128;
    const int trow = (tid >> 4) << 3;
    const int c0   = (tid & 15) << 2;

    const float* Qb = g_Q + ((size_t)(b * Nn) + i0) * 256 + h * 64;
    const float* Kb = g_K + ((size_t)(b * Nn) + j0) * 256 + h * 64;

    // stage full 128x64 tiles: 2048 float4 slots each, 8 per thread
#pragma unroll
    for (int l = 0; l < 8; ++l) {
        int idx = tid + 256 * l;
        int row = idx >> 4;            // 0..127
        int col = (idx & 15) << 2;     // 0..60
        float4 av = *(const float4*)(Qb + (size_t)row * 256 + col);
        float4 bv = *(const float4*)(Kb + (size_t)row * 256 + col);
        As[(col + 0) * 132 + row] = av.x; As[(col + 1) * 132 + row] = av.y;
        As[(col + 2) * 132 + row] = av.z; As[(col + 3) * 132 + row] = av.w;
        Bs[(col + 0) * 132 + row] = bv.x; Bs[(col + 1) * 132 + row] = bv.y;
        Bs[(col + 2) * 132 + row] = bv.z; Bs[(col + 3) * 132 + row] = bv.w;
    }
    __syncthreads();

    unsigned long long acc[8][4];
#pragma unroll
    for (int i = 0; i < 8; ++i)
#pragma unroll
        for (int p = 0; p < 4; ++p) acc[i][p] = 0ULL;

#pragma unroll 8
    for (int kk = 0; kk < 64; ++kk) {
        const float* Ak = As + kk * 132;
        const float* Bk = Bs + kk * 132;
        float4 a0 = *(const float4*)&Ak[trow];
        float4 a1 = *(const float4*)&Ak[trow + 4];
        ulonglong2 b0 = *(const ulonglong2*)&Bk[c0];
        ulonglong2 b1 = *(const ulonglong2*)&Bk[c0 + 64];
        unsigned long long ad[8];
        ad[0] = pack2(a0.x, a0.x); ad[1] = pack2(a0.y, a0.y);
        ad[2] = pack2(a0.z, a0.z); ad[3] = pack2(a0.w, a0.w);
        ad[4] = pack2(a1.x, a1.x); ad[5] = pack2(a1.y, a1.y);
        ad[6] = pack2(a1.z, a1.z); ad[7] = pack2(a1.w, a1.w);
#pragma unroll
        for (int i = 0; i < 8; ++i) {
            fma2(acc[i][0], ad[i], b0.x);
            fma2(acc[i][1], ad[i], b0.y);
            fma2(acc[i][2], ad[i], b1.x);
            fma2(acc[i][3], ad[i], b1.y);
        }
    }

#pragma unroll
    for (int i = 0; i < 8; ++i) {
        int gi = i0 + trow + i;
        const float* tdr = td + ((size_t)b * Nn + gi) * Nn + j0;
        float* Sr = g_S + ((size_t)bh * Nn + gi) * Nn + j0;
        float4 t0 = *(const float4*)&tdr[c0];
        float4 t1 = *(const float4*)&tdr[c0 + 64];
        float2 v0 = unpack2(acc[i][0]), v1 = unpack2(acc[i][1]);
        float2 v2 = unpack2(acc[i][2]), v3 = unpack2(acc[i][3]);
        float4 o0 = make_float4(v0.x * 0.125f - 0.1f * t0.x,
                                v0.y * 0.125f - 0.1f * t0.y,
                                v1.x * 0.125f - 0.1f * t0.z,
                                v1.y * 0.125f - 0.1f * t0.w);
        float4 o1 = make_float4(v2.x * 0.125f - 0.1f * t1.x,
                                v2.y * 0.125f - 0.1f * t1.y,
                                v3.x * 0.125f - 0.1f * t1.z,
                                v3.y * 0.125f - 0.1f * t1.w);
        *(float4*)&Sr[c0]      = o0;
        *(float4*)&Sr[c0 + 64] = o1;
    }
}

// ============================================================================
// Fused: per (b,i): exact top-k threshold (4 heads, one warp each), then
// SPARSE softmax (exp only on ~k survivors), adjacency scatter, sparse attn@V.
// ============================================================================
__global__ void __launch_bounds__(256) fused_attn_kernel(
    const int* __restrict__ topk_ptr, float* __restrict__ out_adj)
{
    __shared__ __align__(16) float sc[4][1024];
    __shared__ __align__(16) float adjs[1024];
    __shared__ __align__(16) float msgs[256];
    __shared__ float s_kth[4];
    __shared__ float s_max[4];
    __shared__ int   s_cnt;
    __shared__ float s_tot;
    __shared__ int   jl[1024];
    __shared__ float av[1024];

    const int tid  = threadIdx.x;
    const int bi   = blockIdx.x;
    const int b    = bi >> 10;
    const int i    = bi & 1023;
    const int warp = tid >> 5, lane = tid & 31;

#pragma unroll
    for (int h = 0; h < 4; ++h) {
        const float4* src = (const float4*)(g_S + (((size_t)(b * 4 + h) * Nn + i) * Nn));
        ((float4*)sc[h])[tid] = src[tid];
    }
    ((float4*)adjs)[tid] = make_float4(0.f, 0.f, 0.f, 0.f);
    msgs[tid] = 0.f;
    __syncthreads();

    int kv = *topk_ptr;
    if (kv > Nn) kv = Nn;
    if (kv < 1)  kv = 1;

    // ---- exact kth-largest per head: warp h owns head h ----
    if (warp < 4) {
        const float* row = sc[warp];
        unsigned u[32];
        float fm = -3.4e38f;
#pragma unroll
        for (int e = 0; e < 32; ++e) {
            float x = row[e * 32 + lane];
            fm = fmaxf(fm, x);
            u[e] = mapf(x);
        }
#pragma unroll
        for (int o = 16; o; o >>= 1) fm = fmaxf(fm, __shfl_xor_sync(0xffffffffu, fm, o));

        unsigned pref = 0, kthU = 0;
        bool got = false;
        for (int bit = 31; bit >= 0; --bit) {
            unsigned cand = pref | (1u << bit);
            int c = 0;
#pragma unroll
            for (int e = 0; e < 32; ++e) c += (u[e] >= cand) ? 1 : 0;
#pragma unroll
            for (int o = 16; o; o >>= 1) c += __shfl_xor_sync(0xffffffffu, c, o);
            if (c == kv) {
                unsigned mn = 0xFFFFFFFFu;
#pragma unroll
                for (int e = 0; e < 32; ++e)
                    if (u[e] >= cand) mn = umin(mn, u[e]);
#pragma unroll
                for (int o = 16; o; o >>= 1) mn = umin(mn, __shfl_xor_sync(0xffffffffu, mn, o));
                kthU = mn; got = true; break;
            }
            if (c > kv) pref = cand;
        }
        if (!got) kthU = pref;
        if (lane == 0) { s_kth[warp] = invmap(kthU); s_max[warp] = fm; }
    }
    __syncthreads();

    // ---- per head: compact survivors, exp only survivors, scatter ----
    for (int h = 0; h < 4; ++h) {
        if (tid == 0) { s_cnt = 0; s_tot = 0.f; }
        __syncthreads();

        const float kth = s_kth[h];
        const float mx  = s_max[h];

        // survivor compaction (~k entries)
#pragma unroll
        for (int r = 0; r < 4; ++r) {
            int j = r * 256 + tid;
            float s = sc[h][j];
            if (s >= kth) {
                int p = atomicAdd(&s_cnt, 1);
                jl[p] = j;
                av[p] = s;
            }
        }
        __syncthreads();
        const int cnt = s_cnt;

        // exp + sum over survivors only
        float lsum = 0.f;
        for (int l = tid; l < cnt; l += 256) {
            float e = __expf(av[l] - mx);
            av[l] = e;
            lsum += e;
        }
#pragma unroll
        for (int o = 16; o; o >>= 1) lsum += __shfl_xor_sync(0xffffffffu, lsum, o);
        if (lane == 0 && lsum != 0.f) atomicAdd(&s_tot, lsum);
        __syncthreads();

        const float inv = 1.f / s_tot;  // max survives -> s_tot >= 1

        // normalize + adjacency scatter (distinct j within head -> race-free)
        for (int l = tid; l < cnt; l += 256) {
            float a = av[l] * inv;
            av[l] = a;
            adjs[jl[l]] += 0.25f * a;
        }
        __syncthreads();

        // sparse attn @ V
        const int d    = tid & 63;
        const int part = tid >> 6;
        const float* vb = g_V + (size_t)b * Nn * 256 + h * 64 + d;
        float acc = 0.f;
        for (int l = part; l < cnt; l += 4) {
            acc = fmaf(av[l], __ldg(&vb[(size_t)jl[l] * 256]), acc);
        }
        if (acc != 0.f) atomicAdd(&msgs[(h << 6) + d], acc);
        __syncthreads();
    }

    float* arow = out_adj + ((size_t)(b * Nn) + i) * Nn;
    ((float4*)arow)[tid] = ((const float4*)adjs)[tid];
    g_M[((size_t)(b * Nn) + i) * 256 + tid] = msgs[tid];
}

// ============================================================================
extern "C" void kernel_launch(void* const* d_in, const int* in_sizes, int n_in,
                              void* d_out, int out_size)
{
    const float* h_in = (const float*)d_in[0];
    const float* td   = (const float*)d_in[1];
    const float* Wq   = (const float*)d_in[2];
    const float* bq   = (const float*)d_in[3];
    const float* Wk   = (const float*)d_in[4];
    const float* bk   = (const float*)d_in[5];
    const float* Wv   = (const float*)d_in[6];
    const float* bv   = (const float*)d_in[7];
    const float* Wo   = (const float*)d_in[8];
    const float* bo   = (const float*)d_in[9];
    const int*   tk   = (const int*)d_in[10];

    float* out_adj = (float*)d_out;
    float* out_msg = out_adj + (size_t)Bn * Nn * Nn;

    float *q, *k, *v, *m;
    cudaGetSymbolAddress((void**)&q, g_Q);
    cudaGetSymbolAddress((void**)&k, g_K);
    cudaGetSymbolAddress((void**)&v, g_V);
    cudaGetSymbolAddress((void**)&m, g_M);

    static bool attr_done = false;
    if (!attr_done) {
        cudaFuncSetAttribute(scores_kernel,
                             cudaFuncAttributeMaxDynamicSharedMemorySize, SCORES_SMEM);
        attr_done = true;
    }

    dim3 gp(Dn / 128, ROWS / 128);  // (2, 64)
    gemm256_kernel<<<gp, 256>>>(h_in, Wq, bq, q);
    gemm256_kernel<<<gp, 256>>>(h_in, Wk, bk, k);
    gemm256_kernel<<<gp, 256>>>(h_in, Wv, bv, v);
    scores_kernel<<<dim3(Nn / 128, Nn / 128, Bn * Hn), 256, SCORES_SMEM>>>(td);
    fused_attn_kernel<<<ROWS, 256>>>(tk, out_adj);
    gemm256_kernel<<<gp, 256>>>(m, Wo, bo, out_msg);
}